// round 4
// baseline (speedup 1.0000x reference)
#include <cuda_runtime.h>

// CapLayer fused capsule routing. 512 threads/CTA, 2 CTAs/SM, vectorized LDS/LDG.
// x:    d_in[0]  float [512][256][6][6]   (channel = g*8+k, g<32, k<8)
// W:    d_in[2]  float [5120][8] ; flat = g*1280 + j*128 + d*8 + k
// bias: d_in[3]  float [5120]    ; flat = g*160  + j*16  + d
// out:  float [512][10][16]

#define LOG2E 1.4426950408889634f

struct Smem {
    float x[32 * 8 * 36];     // 9216  [g][k][hw]
    float cbuf[16 * 10 * 36]; // 5760  per-warp c scratch [w][j][hw]
    float vW[10 * 32 * 8];    // 2560  [j][g][k]  (accum, pre-scaled by log2e)
    float vb[10 * 32];        // 320   [j][g]
    float cx[10 * 32 * 8];    // 2560  [j][g][k]
    float csum[10 * 32];      // 320   [j][g]
    float sW[160];
    float sB[160];
    float v[160];
    float xsum[256];          // [g][k]
};                            // 21472 floats = 85888 B  (2 CTAs/SM)

__device__ __forceinline__ float ex2_approx(float x) {
    float y; asm("ex2.approx.ftz.f32 %0, %1;" : "=f"(y) : "f"(x)); return y;
}
__device__ __forceinline__ float rcp_approx(float x) {
    float y; asm("rcp.approx.ftz.f32 %0, %1;" : "=f"(y) : "f"(x)); return y;
}
__device__ __forceinline__ float dot4(float4 a, float4 b) {
    return a.x * b.x + a.y * b.y + a.z * b.z + a.w * b.w;
}
__device__ __forceinline__ float sum4(float4 a) {
    return a.x + a.y + a.z + a.w;
}

__global__ __launch_bounds__(512, 2)
void caps_kernel(const float* __restrict__ x_g,
                 const float* __restrict__ W,
                 const float* __restrict__ bias,
                 float* __restrict__ out) {
    extern __shared__ float smem_raw[];
    Smem* S = reinterpret_cast<Smem*>(smem_raw);

    const int b    = blockIdx.x;
    const int tid  = threadIdx.x;
    const int w    = tid >> 5;
    const int lane = tid & 31;

    // ---- load x ([g][k][hw] contiguous) ----
    {
        const float4* src = reinterpret_cast<const float4*>(x_g + (size_t)b * 9216);
        float4* dst = reinterpret_cast<float4*>(S->x);
        #pragma unroll
        for (int i = 0; i < 5; i++) {
            int idx = tid + i * 512;
            if (idx < 2304) dst[idx] = src[idx];
        }
    }
    __syncthreads();

    // ---- xsum[g][k] = sum_hw x ----
    if (tid < 256) {
        const float4* p = reinterpret_cast<const float4*>(S->x + tid * 36);
        float4 a4 = p[0];
        #pragma unroll
        for (int t = 1; t < 9; t++) {
            float4 q = p[t];
            a4.x += q.x; a4.y += q.y; a4.z += q.z; a4.w += q.w;
        }
        S->xsum[tid] = sum4(a4);
    }
    __syncthreads();

    // iter 1: c uniform 0.1 -> cx = 0.1*xsum, csum = 3.6
    for (int i = tid; i < 2560; i += 512) S->cx[i] = 0.1f * S->xsum[i & 255];
    if (tid < 320) S->csum[tid] = 3.6f;
    __syncthreads();

    for (int it = 0; it < 3; ++it) {
        if (it > 0) {
            // ===== Phase A+B per warp; warp handles groups w and w+16 =====
            #pragma unroll
            for (int gi = 0; gi < 2; gi++) {
                const int g = w + gi * 16;
                // --- Phase A: logits -> softmax over j -> c (per-warp buffer) ---
                {
                    const float* xr = S->x + g * 8 * 36;
                    float xv[8], xv2[8];
                    #pragma unroll
                    for (int k = 0; k < 8; k++) {
                        xv[k]  = xr[k * 36 + lane];
                        xv2[k] = xr[k * 36 + 32 + (lane & 3)];
                    }
                    float bb[10], bb2[10];
                    #pragma unroll
                    for (int j = 0; j < 10; j++) {
                        const float4* vwp = reinterpret_cast<const float4*>(S->vW + j * 256 + g * 8);
                        float4 w0 = vwp[0], w1 = vwp[1];
                        float t0 = S->vb[j * 32 + g];
                        float a  = t0, a2 = t0;
                        a  += w0.x*xv[0] + w0.y*xv[1] + w0.z*xv[2] + w0.w*xv[3]
                            + w1.x*xv[4] + w1.y*xv[5] + w1.z*xv[6] + w1.w*xv[7];
                        a2 += w0.x*xv2[0] + w0.y*xv2[1] + w0.z*xv2[2] + w0.w*xv2[3]
                            + w1.x*xv2[4] + w1.y*xv2[5] + w1.z*xv2[6] + w1.w*xv2[7];
                        bb[j] = a; bb2[j] = a2;
                    }
                    float Z = 0.f, Z2 = 0.f;
                    #pragma unroll
                    for (int j = 0; j < 10; j++) {
                        bb[j]  = ex2_approx(bb[j]);   Z  += bb[j];
                        bb2[j] = ex2_approx(bb2[j]);  Z2 += bb2[j];
                    }
                    float r  = rcp_approx(Z);
                    float r2 = rcp_approx(Z2);
                    float* cw = S->cbuf + w * 360;
                    #pragma unroll
                    for (int j = 0; j < 10; j++) {
                        cw[j * 36 + lane] = bb[j] * r;
                        if (lane < 4) cw[j * 36 + 32 + lane] = bb2[j] * r2;
                    }
                }
                __syncwarp();
                // --- Phase B: cx[j][g][k] = sum_hw c*x ; csum[j][g] = sum_hw c ---
                // lane (k,q): hw chunks {4q..4q+3} U {16+4q..16+4q+3} U {32+q}
                {
                    const int k = lane >> 2, q = lane & 3;
                    const float* xr = S->x + (g * 8 + k) * 36;
                    float4 x0 = *reinterpret_cast<const float4*>(xr + 4 * q);
                    float4 x1 = *reinterpret_cast<const float4*>(xr + 16 + 4 * q);
                    float  x2 = xr[32 + q];
                    const float* cb = S->cbuf + w * 360;
                    float acc[10], cs[10];
                    #pragma unroll
                    for (int j = 0; j < 10; j++) {
                        float4 c0 = *reinterpret_cast<const float4*>(cb + j * 36 + 4 * q);
                        float4 c1 = *reinterpret_cast<const float4*>(cb + j * 36 + 16 + 4 * q);
                        float  c2 = cb[j * 36 + 32 + q];
                        acc[j] = dot4(c0, x0) + dot4(c1, x1) + c2 * x2;
                        cs[j]  = sum4(c0) + sum4(c1) + c2;
                    }
                    #pragma unroll
                    for (int j = 0; j < 10; j++) {
                        acc[j] += __shfl_xor_sync(0xffffffffu, acc[j], 1);
                        acc[j] += __shfl_xor_sync(0xffffffffu, acc[j], 2);
                        cs[j]  += __shfl_xor_sync(0xffffffffu, cs[j], 1);
                        cs[j]  += __shfl_xor_sync(0xffffffffu, cs[j], 2);
                    }
                    if (q == 0) {
                        #pragma unroll
                        for (int j = 0; j < 10; j++) S->cx[j * 256 + g * 8 + k] = acc[j];
                        if (k == 0) {
                            #pragma unroll
                            for (int j = 0; j < 10; j++) S->csum[j * 32 + g] = cs[j];
                        }
                    }
                }
                __syncwarp();
            }
            __syncthreads();
        }

        // ===== Phase C: sW[p] = sum_{g,k} W*cx (vectorized over k) =====
        {
            const int o  = tid >> 3;     // octet 0..63
            const int l8 = tid & 7;      // lane in octet -> base group
            #pragma unroll
            for (int pi = 0; pi < 3; pi++) {
                if (pi < 2 || o < 32) {
                    const int p = o + pi * 64;
                    const int j = p >> 4;
                    float acc = 0.f;
                    #pragma unroll
                    for (int gg = 0; gg < 4; gg++) {
                        const int g = l8 + gg * 8;
                        const float4* wp  = reinterpret_cast<const float4*>(W + g * 1280 + p * 8);
                        const float4* cxp = reinterpret_cast<const float4*>(S->cx + j * 256 + g * 8);
                        acc += dot4(wp[0], cxp[0]) + dot4(wp[1], cxp[1]);
                    }
                    acc += __shfl_xor_sync(0xffffffffu, acc, 1);
                    acc += __shfl_xor_sync(0xffffffffu, acc, 2);
                    acc += __shfl_xor_sync(0xffffffffu, acc, 4);
                    if (l8 == 0) S->sW[p] = acc;
                }
            }
            // bias part on warps 11-15: thread per pair
            if (tid >= 352) {
                const int p = tid - 352;
                const int j = p >> 4;
                const float4* cs4 = reinterpret_cast<const float4*>(S->csum + j * 32);
                float accb = 0.f;
                #pragma unroll
                for (int gg = 0; gg < 8; gg++) {
                    float4 c4 = cs4[gg];
                    accb += bias[(gg * 4 + 0) * 160 + p] * c4.x
                          + bias[(gg * 4 + 1) * 160 + p] * c4.y
                          + bias[(gg * 4 + 2) * 160 + p] * c4.z
                          + bias[(gg * 4 + 3) * 160 + p] * c4.w;
                }
                S->sB[p] = accb;
            }
        }
        __syncthreads();

        // ===== Phase D: squash =====
        if (tid < 160) {
            const int p = tid;
            float sv = S->sW[p] + S->sB[p];
            float n2 = sv * sv;
            n2 += __shfl_xor_sync(0xffffffffu, n2, 1);
            n2 += __shfl_xor_sync(0xffffffffu, n2, 2);
            n2 += __shfl_xor_sync(0xffffffffu, n2, 4);
            n2 += __shfl_xor_sync(0xffffffffu, n2, 8);
            float f  = __fdividef(sqrtf(n2), 1.0f + n2);
            float vv = sv * f;
            S->v[p] = vv;
            if (it == 2) out[(size_t)b * 160 + p] = vv;
        }

        if (it < 2) {
            __syncthreads();
            // ===== Phase E (vectorized): vW octets + vb =====
            if (tid < 320) {
                const int j = tid >> 5, g = tid & 31;
                const float4* vj = reinterpret_cast<const float4*>(S->v + j * 16);
                float4 v0 = vj[0], v1 = vj[1], v2 = vj[2], v3 = vj[3];
                const float vd[16] = {v0.x,v0.y,v0.z,v0.w, v1.x,v1.y,v1.z,v1.w,
                                      v2.x,v2.y,v2.z,v2.w, v3.x,v3.y,v3.z,v3.w};
                const float4* wp = reinterpret_cast<const float4*>(W + g * 1280 + j * 128);
                float4 o0 = {0,0,0,0}, o1 = {0,0,0,0};
                #pragma unroll
                for (int d = 0; d < 16; d++) {
                    float4 wa = wp[d * 2], wb = wp[d * 2 + 1];
                    o0.x += vd[d]*wa.x; o0.y += vd[d]*wa.y; o0.z += vd[d]*wa.z; o0.w += vd[d]*wa.w;
                    o1.x += vd[d]*wb.x; o1.y += vd[d]*wb.y; o1.z += vd[d]*wb.z; o1.w += vd[d]*wb.w;
                }
                o0.x *= LOG2E; o0.y *= LOG2E; o0.z *= LOG2E; o0.w *= LOG2E;
                o1.x *= LOG2E; o1.y *= LOG2E; o1.z *= LOG2E; o1.w *= LOG2E;
                float4* dst = reinterpret_cast<float4*>(S->vW + j * 256 + g * 8);
                if (it == 0) { dst[0] = o0; dst[1] = o1; }
                else {
                    float4 a0 = dst[0], a1 = dst[1];
                    a0.x += o0.x; a0.y += o0.y; a0.z += o0.z; a0.w += o0.w;
                    a1.x += o1.x; a1.y += o1.y; a1.z += o1.z; a1.w += o1.w;
                    dst[0] = a0; dst[1] = a1;
                }
            } else {
                const int u = tid - 320;     // 0..191
                // disjoint partition of 0..319: {u} and {u+192 for u<128}
                #pragma unroll
                for (int rep = 0; rep < 2; rep++) {
                    const int vbi = u + rep * 192;
                    if (vbi < 320) {
                        const int j = vbi >> 5, g = vbi & 31;
                        const float4* bp = reinterpret_cast<const float4*>(bias + g * 160 + j * 16);
                        const float4* vj = reinterpret_cast<const float4*>(S->v + j * 16);
                        float a = dot4(bp[0], vj[0]) + dot4(bp[1], vj[1])
                                + dot4(bp[2], vj[2]) + dot4(bp[3], vj[3]);
                        a *= LOG2E;
                        if (it == 0) S->vb[vbi] = a;
                        else         S->vb[vbi] += a;
                    }
                }
            }
            __syncthreads();
        }
    }
}

extern "C" void kernel_launch(void* const* d_in, const int* in_sizes, int n_in,
                              void* d_out, int out_size) {
    const float* x    = (const float*)d_in[0];
    const float* W    = (const float*)d_in[2];
    const float* bias = (const float*)d_in[3];
    float* out = (float*)d_out;

    cudaFuncSetAttribute(caps_kernel,
                         cudaFuncAttributeMaxDynamicSharedMemorySize,
                         (int)sizeof(Smem));
    caps_kernel<<<512, 512, sizeof(Smem)>>>(x, W, bias, out);
}

// round 5
// speedup vs baseline: 1.6592x; 1.6592x over previous
#include <cuda_runtime.h>

// CapLayer fused capsule routing. 512 threads/CTA, 2 CTAs/SM.
// Coalesced W streams (warp covers contiguous bytes), vectorized LDS in A/B.
// x:    d_in[0]  float [512][256][6][6]   (channel = g*8+k, g<32, k<8)
// W:    d_in[2]  float [5120][8] ; flat = g*1280 + j*128 + d*8 + k
// bias: d_in[3]  float [5120]    ; flat = g*160  + j*16  + d
// out:  float [512][10][16]

#define LOG2E 1.4426950408889634f

struct Smem {
    float x[32 * 8 * 36];     // 9216  [g][k][hw]
    float cbuf[16 * 10 * 36]; // 5760  per-warp c scratch [w][j][hw]
    float vW[10 * 32 * 8];    // 2560  [j][g][k]  (accum, pre-scaled by log2e)
    float vb[10 * 32];        // 320   [j][g]
    float cx[10 * 32 * 8];    // 2560  [j][g][k]
    float csum[10 * 32];      // 320   [j][g]
    float sW[160];
    float sB[160];
    float v[160];
    float xsum[256];          // [g][k]
};                            // 21472 floats = 85888 B  (2 CTAs/SM)

__device__ __forceinline__ float ex2_approx(float x) {
    float y; asm("ex2.approx.ftz.f32 %0, %1;" : "=f"(y) : "f"(x)); return y;
}
__device__ __forceinline__ float rcp_approx(float x) {
    float y; asm("rcp.approx.ftz.f32 %0, %1;" : "=f"(y) : "f"(x)); return y;
}
__device__ __forceinline__ float dot4(float4 a, float4 b) {
    return a.x * b.x + a.y * b.y + a.z * b.z + a.w * b.w;
}
__device__ __forceinline__ float sum4(float4 a) {
    return a.x + a.y + a.z + a.w;
}

__global__ __launch_bounds__(512, 2)
void caps_kernel(const float* __restrict__ x_g,
                 const float* __restrict__ W,
                 const float* __restrict__ bias,
                 float* __restrict__ out) {
    extern __shared__ float smem_raw[];
    Smem* S = reinterpret_cast<Smem*>(smem_raw);

    const int b    = blockIdx.x;
    const int tid  = threadIdx.x;
    const int w    = tid >> 5;
    const int lane = tid & 31;

    // ---- load x ([g][k][hw] contiguous) ----
    {
        const float4* src = reinterpret_cast<const float4*>(x_g + (size_t)b * 9216);
        float4* dst = reinterpret_cast<float4*>(S->x);
        #pragma unroll
        for (int i = 0; i < 5; i++) {
            int idx = tid + i * 512;
            if (idx < 2304) dst[idx] = src[idx];
        }
    }
    __syncthreads();

    // ---- xsum[g][k] = sum_hw x ----
    if (tid < 256) {
        const float4* p = reinterpret_cast<const float4*>(S->x + tid * 36);
        float4 a4 = p[0];
        #pragma unroll
        for (int t = 1; t < 9; t++) {
            float4 q = p[t];
            a4.x += q.x; a4.y += q.y; a4.z += q.z; a4.w += q.w;
        }
        S->xsum[tid] = sum4(a4);
    }
    __syncthreads();

    // iter 1: c uniform 0.1 -> cx = 0.1*xsum (all j), csum = 3.6
    for (int i = tid; i < 2560; i += 512) S->cx[i] = 0.1f * S->xsum[i & 255];
    if (tid < 320) S->csum[tid] = 3.6f;
    __syncthreads();

    for (int it = 0; it < 3; ++it) {
        if (it > 0) {
            // ===== Phase A+B per warp; warp handles groups w and w+16 =====
            #pragma unroll
            for (int gi = 0; gi < 2; gi++) {
                const int g = w + gi * 16;
                // --- Phase A: logits -> softmax over j -> c (per-warp buffer) ---
                {
                    const float* xr = S->x + g * 8 * 36;
                    float xv[8], xv2[8];
                    #pragma unroll
                    for (int k = 0; k < 8; k++) {
                        xv[k]  = xr[k * 36 + lane];
                        xv2[k] = xr[k * 36 + 32 + (lane & 3)];
                    }
                    float bb[10], bb2[10];
                    #pragma unroll
                    for (int j = 0; j < 10; j++) {
                        const float4* vwp = reinterpret_cast<const float4*>(S->vW + j * 256 + g * 8);
                        float4 w0 = vwp[0], w1 = vwp[1];   // warp-uniform broadcast
                        float t0 = S->vb[j * 32 + g];
                        float a  = t0, a2 = t0;
                        a  += w0.x*xv[0] + w0.y*xv[1] + w0.z*xv[2] + w0.w*xv[3]
                            + w1.x*xv[4] + w1.y*xv[5] + w1.z*xv[6] + w1.w*xv[7];
                        a2 += w0.x*xv2[0] + w0.y*xv2[1] + w0.z*xv2[2] + w0.w*xv2[3]
                            + w1.x*xv2[4] + w1.y*xv2[5] + w1.z*xv2[6] + w1.w*xv2[7];
                        bb[j] = a; bb2[j] = a2;
                    }
                    float Z = 0.f, Z2 = 0.f;
                    #pragma unroll
                    for (int j = 0; j < 10; j++) {
                        bb[j]  = ex2_approx(bb[j]);   Z  += bb[j];
                        bb2[j] = ex2_approx(bb2[j]);  Z2 += bb2[j];
                    }
                    float r  = rcp_approx(Z);
                    float r2 = rcp_approx(Z2);
                    float* cw = S->cbuf + w * 360;
                    #pragma unroll
                    for (int j = 0; j < 10; j++) {
                        cw[j * 36 + lane] = bb[j] * r;
                        if (lane < 4) cw[j * 36 + 32 + lane] = bb2[j] * r2;
                    }
                }
                __syncwarp();
                // --- Phase B: cx[j][g][k] = sum_hw c*x ; csum[j][g] = sum_hw c ---
                // lane (k,q): hw chunks {4q..4q+3} U {16+4q..16+4q+3} U {32+q}
                {
                    const int k = lane >> 2, q = lane & 3;
                    const float* xr = S->x + (g * 8 + k) * 36;
                    float4 x0 = *reinterpret_cast<const float4*>(xr + 4 * q);
                    float4 x1 = *reinterpret_cast<const float4*>(xr + 16 + 4 * q);
                    float  x2 = xr[32 + q];
                    const float* cb = S->cbuf + w * 360;
                    float acc[10], cs[10];
                    #pragma unroll
                    for (int j = 0; j < 10; j++) {
                        float4 c0 = *reinterpret_cast<const float4*>(cb + j * 36 + 4 * q);
                        float4 c1 = *reinterpret_cast<const float4*>(cb + j * 36 + 16 + 4 * q);
                        float  c2 = cb[j * 36 + 32 + q];
                        acc[j] = dot4(c0, x0) + dot4(c1, x1) + c2 * x2;
                        cs[j]  = sum4(c0) + sum4(c1) + c2;
                    }
                    #pragma unroll
                    for (int j = 0; j < 10; j++) {
                        acc[j] += __shfl_xor_sync(0xffffffffu, acc[j], 1);
                        acc[j] += __shfl_xor_sync(0xffffffffu, acc[j], 2);
                        cs[j]  += __shfl_xor_sync(0xffffffffu, cs[j], 1);
                        cs[j]  += __shfl_xor_sync(0xffffffffu, cs[j], 2);
                    }
                    if (q == 0) {
                        #pragma unroll
                        for (int j = 0; j < 10; j++) S->cx[j * 256 + g * 8 + k] = acc[j];
                        if (k == 0) {
                            #pragma unroll
                            for (int j = 0; j < 10; j++) S->csum[j * 32 + g] = cs[j];
                        }
                    }
                }
                __syncwarp();
            }
            __syncthreads();
        }

        // ===== Phase C: sW[p] = sum_{g,k} W*cx =====
        // threads 0..319: 2 threads per pair p (kh = k-half, float4 each).
        // Warp w covers p in [w*16, w*16+16) -> j = w. Per g, the warp's 32
        // lanes read 32 CONSECUTIVE float4s of W (512B contiguous).
        if (tid < 320) {
            const int p  = tid >> 1;
            const int kh = tid & 1;
            const int j  = p >> 4;
            const float4* Wv  = reinterpret_cast<const float4*>(W);
            const float4* cxv = reinterpret_cast<const float4*>(S->cx);
            float acc = 0.f;
            #pragma unroll 8
            for (int g = 0; g < 32; g++)
                acc += dot4(Wv[g * 320 + p * 2 + kh], cxv[j * 64 + g * 2 + kh]);
            acc += __shfl_xor_sync(0xffffffffu, acc, 1);
            if (kh == 0) S->sW[p] = acc;
        } else {
            // bias part on warps 10-15: thread per pair (coalesced in p)
            const int p = tid - 352;
            if (p >= 0) {
                const int j = p >> 4;
                const float4* cs4 = reinterpret_cast<const float4*>(S->csum + j * 32);
                float accb = 0.f;
                #pragma unroll
                for (int gg = 0; gg < 8; gg++) {
                    float4 c4 = cs4[gg];
                    accb += bias[(gg * 4 + 0) * 160 + p] * c4.x
                          + bias[(gg * 4 + 1) * 160 + p] * c4.y
                          + bias[(gg * 4 + 2) * 160 + p] * c4.z
                          + bias[(gg * 4 + 3) * 160 + p] * c4.w;
                }
                S->sB[p] = accb;
            }
        }
        __syncthreads();

        // ===== Phase D: squash =====
        if (tid < 160) {
            const int p = tid;
            float sv = S->sW[p] + S->sB[p];
            float n2 = sv * sv;
            n2 += __shfl_xor_sync(0xffffffffu, n2, 1);
            n2 += __shfl_xor_sync(0xffffffffu, n2, 2);
            n2 += __shfl_xor_sync(0xffffffffu, n2, 4);
            n2 += __shfl_xor_sync(0xffffffffu, n2, 8);
            float f  = __fdividef(sqrtf(n2), 1.0f + n2);
            float vv = sv * f;
            S->v[p] = vv;
            if (it == 2) out[(size_t)b * 160 + p] = vv;
        }

        if (it < 2) {
            __syncthreads();
            // ===== Phase E (scalar, coalesced): vW and vb accumulate =====
            for (int idx = tid; idx < 2880; idx += 512) {
                if (idx < 2560) {
                    const int j = idx >> 8;
                    const int g = (idx >> 3) & 31, k = idx & 7;
                    const float* wp = W + g * 1280 + j * 128 + k;
                    float a = 0.f;
                    #pragma unroll
                    for (int d = 0; d < 16; d++) a += S->v[j * 16 + d] * wp[d * 8];
                    S->vW[idx] = (it == 0) ? LOG2E * a : S->vW[idx] + LOG2E * a;
                } else {
                    const int t2 = idx - 2560;
                    const int j = t2 >> 5, g = t2 & 31;
                    const float* bp = bias + g * 160 + j * 16;
                    float a = 0.f;
                    #pragma unroll
                    for (int d = 0; d < 16; d++) a += S->v[j * 16 + d] * bp[d];
                    S->vb[t2] = (it == 0) ? LOG2E * a : S->vb[t2] + LOG2E * a;
                }
            }
            __syncthreads();
        }
    }
}

extern "C" void kernel_launch(void* const* d_in, const int* in_sizes, int n_in,
                              void* d_out, int out_size) {
    const float* x    = (const float*)d_in[0];
    const float* W    = (const float*)d_in[2];
    const float* bias = (const float*)d_in[3];
    float* out = (float*)d_out;

    cudaFuncSetAttribute(caps_kernel,
                         cudaFuncAttributeMaxDynamicSharedMemorySize,
                         (int)sizeof(Smem));
    caps_kernel<<<512, 512, sizeof(Smem)>>>(x, W, bias, out);
}